// round 6
// baseline (speedup 1.0000x reference)
#include <cuda_runtime.h>
#include <cuda_bf16.h>
#include <cstdint>

#define NN 100000
#define EE 1600000
#define GG 128
#define IND 329
#define NEG 0.2f

// ---------------- device scratch (no allocation allowed) ----------------
__device__ __align__(256) __nv_bfloat16 g_xp[(size_t)NN * 256];   // 51.2 MB bf16 features [N][H*C]
__device__ __align__(256) float g_asrc[NN * 4];
__device__ __align__(256) float g_adst[NN * 4];
__device__ __align__(256) float g_denom[NN * 4];
__device__ __align__(256) float g_selfex[NN * 4];
__device__ __align__(256) float g_out[(size_t)NN * 64];           // 25.6 MB head-summed aggregate
__device__ __align__(256) float g_pool[GG * 64];
__device__ __align__(256) float g_cnt[GG];
__device__ int g_e64;   // 1 if edge_index is int64, 0 if int32
__device__ int g_b64;   // 1 if batch is int64, 0 if int32

// ---------------- small helpers ----------------
__device__ __forceinline__ unsigned long long pk2(float lo, float hi) {
    unsigned long long r;
    asm("mov.b64 %0,{%1,%2};" : "=l"(r) : "f"(lo), "f"(hi));
    return r;
}
__device__ __forceinline__ void upk2(unsigned long long v, float& lo, float& hi) {
    asm("mov.b64 {%0,%1},%2;" : "=f"(lo), "=f"(hi) : "l"(v));
}
__device__ __forceinline__ unsigned long long ffma2(unsigned long long a, unsigned long long b,
                                                    unsigned long long c) {
    unsigned long long d;
    asm("fma.rn.f32x2 %0,%1,%2,%3;" : "=l"(d) : "l"(a), "l"(b), "l"(c));
    return d;
}
__device__ __forceinline__ float2 bf2f(unsigned u) {
    __nv_bfloat162 b = *reinterpret_cast<const __nv_bfloat162*>(&u);
    return __bfloat1622float2(b);
}
__device__ __forceinline__ float lrelu(float x) { return x > 0.f ? x : NEG * x; }
__device__ __forceinline__ void red4(float* p, float a, float b, float c, float d) {
    asm volatile("red.global.add.v4.f32 [%0], {%1,%2,%3,%4};"
                 :: "l"(p), "f"(a), "f"(b), "f"(c), "f"(d) : "memory");
}
// dtype-flexible index load, clamped to [0, lim-1]
__device__ __forceinline__ int ldidx(const void* p, long long i, int is64, int lim) {
    long long v = is64 ? ((const long long*)p)[i] : (long long)((const int*)p)[i];
    if (v < 0) v = 0;
    if (v >= lim) v = lim - 1;
    return (int)v;
}

// ---------------- K-1: dtype detector (int32 vs int64) ----------------
__global__ void k_detect(const int* __restrict__ ei_raw, const int* __restrict__ bat_raw) {
    __shared__ int nz_e, nz_b;
    int t = threadIdx.x;  // 256 threads
    if (t == 0) { nz_e = 0; nz_b = 0; }
    __syncthreads();
    // edges: odd 32-bit words among the first 512 words (in-bounds in both layouts).
    // int64 -> high words == 0 always; int32 -> random edge IDs, nonzero w.h.p.
    if (ei_raw[2 * t + 1] != 0) atomicOr(&nz_e, 1);
    // batch: odd words near the END of the int32-word range [0, NN).
    // int64 -> high words == 0; int32 -> sorted batch IDs ~127 there, nonzero.
    if (bat_raw[NN - 1 - 2 * t] != 0) atomicOr(&nz_b, 1);
    __syncthreads();
    if (t == 0) { g_e64 = nz_e ? 0 : 1; g_b64 = nz_b ? 0 : 1; }
}

// ---------------- K0: zero accumulators ----------------
__global__ void k_zero() {
    int i = blockIdx.x * blockDim.x + threadIdx.x;
    int stride = gridDim.x * blockDim.x;
    float4 z = make_float4(0.f, 0.f, 0.f, 0.f);
    float4* o = (float4*)g_out;
    for (int j = i; j < NN * 64 / 4; j += stride) o[j] = z;
    if (i < GG * 64 / 4) ((float4*)g_pool)[i] = z;
    if (i < GG / 4) ((float4*)g_cnt)[i] = z;
}

// ---------------- K1: SGEMM xp = x @ W, fp32 accum via fma.rn.f32x2, bf16 store ----------------
// BM=128, BN=128, BK=8, 256 threads, 8x8 per thread (as 8x4 f32x2 pairs)
__global__ __launch_bounds__(256) void k_gemm(const float* __restrict__ x,
                                              const float* __restrict__ W) {
    __shared__ float As[8][132];
    __shared__ float Bs[8][132];
    int tid = threadIdx.x;
    int rowBase = blockIdx.x * 128;
    int colBase = blockIdx.y * 128;
    int ty = tid >> 4, tx = tid & 15;

    unsigned long long acc[8][4];
#pragma unroll
    for (int i = 0; i < 8; i++)
#pragma unroll
        for (int j = 0; j < 4; j++) acc[i][j] = 0ull;

    int am = tid >> 1;
    int ak = (tid & 1) * 4;
    int bk = tid >> 5;
    int bn = (tid & 31) * 4;
    int arow = rowBase + am;

    for (int kt = 0; kt < 42; kt++) {
        int k0 = kt * 8;
#pragma unroll
        for (int i = 0; i < 4; i++) {
            int kk = k0 + ak + i;
            float v = 0.f;
            if (arow < NN && kk < IND) v = x[(size_t)arow * IND + kk];
            As[ak + i][am] = v;
        }
        {
            int kk = k0 + bk;
            float4 v = make_float4(0.f, 0.f, 0.f, 0.f);
            if (kk < IND) v = *(const float4*)&W[(size_t)kk * 256 + colBase + bn];
            *(float4*)&Bs[bk][bn] = v;
        }
        __syncthreads();
#pragma unroll
        for (int k = 0; k < 8; k++) {
            unsigned long long b[4];
#pragma unroll
            for (int j = 0; j < 4; j++)
                b[j] = *(const unsigned long long*)&Bs[k][tx * 8 + j * 2];
#pragma unroll
            for (int i = 0; i < 8; i++) {
                float av = As[k][ty * 8 + i];
                unsigned long long ad = pk2(av, av);
#pragma unroll
                for (int j = 0; j < 4; j++) acc[i][j] = ffma2(ad, b[j], acc[i][j]);
            }
        }
        __syncthreads();
    }
#pragma unroll
    for (int i = 0; i < 8; i++) {
        int r = rowBase + ty * 8 + i;
        if (r < NN) {
            unsigned o[4];
#pragma unroll
            for (int j = 0; j < 4; j++) {
                float lo, hi;
                upk2(acc[i][j], lo, hi);
                __nv_bfloat162 bb = __floats2bfloat162_rn(lo, hi);
                o[j] = *reinterpret_cast<unsigned*>(&bb);
            }
            uint4 ov = make_uint4(o[0], o[1], o[2], o[3]);
            *(uint4*)&g_xp[(size_t)r * 256 + colBase + tx * 8] = ov;
        }
    }
}

// ---------------- K1b: per-node attention scalars + self-loop softmax init ----------------
__global__ void k_attn(const float* __restrict__ att_src, const float* __restrict__ att_dst) {
    int w = (blockIdx.x * blockDim.x + threadIdx.x) >> 5;
    int lane = threadIdx.x & 31;
    if (w >= NN) return;
    float4 s0 = *(const float4*)&att_src[lane * 8];
    float4 s1 = *(const float4*)&att_src[lane * 8 + 4];
    float4 d0 = *(const float4*)&att_dst[lane * 8];
    float4 d1 = *(const float4*)&att_dst[lane * 8 + 4];
    uint4 raw = *(const uint4*)&g_xp[(size_t)w * 256 + lane * 8];
    float2 p0 = bf2f(raw.x), p1 = bf2f(raw.y), p2 = bf2f(raw.z), p3 = bf2f(raw.w);
    float sdot = p0.x * s0.x + p0.y * s0.y + p1.x * s0.z + p1.y * s0.w
               + p2.x * s1.x + p2.y * s1.y + p3.x * s1.z + p3.y * s1.w;
    float ddot = p0.x * d0.x + p0.y * d0.y + p1.x * d0.z + p1.y * d0.w
               + p2.x * d1.x + p2.y * d1.y + p3.x * d1.z + p3.y * d1.w;
#pragma unroll
    for (int off = 1; off < 8; off <<= 1) {
        sdot += __shfl_xor_sync(0xffffffffu, sdot, off);
        ddot += __shfl_xor_sync(0xffffffffu, ddot, off);
    }
    if ((lane & 7) == 0) {
        int h = lane >> 3;
        g_asrc[w * 4 + h] = sdot;
        g_adst[w * 4 + h] = ddot;
        float ex = __expf(lrelu(sdot + ddot));     // self-loop term
        g_selfex[w * 4 + h] = ex;
        g_denom[w * 4 + h] = ex;                   // denom init = self term
    }
}

// ---------------- K2: edge softmax denominator (max-subtraction is a provable no-op) ----------------
__global__ void k_edge_denom(const void* __restrict__ ei) {
    int e = blockIdx.x * 256 + threadIdx.x;
    if (e >= EE) return;
    int f = g_e64;
    int s = ldidx(ei, e, f, NN);
    int d = ldidx(ei, (long long)EE + e, f, NN);
    float4 as = *(const float4*)&g_asrc[s * 4];
    float4 ad = *(const float4*)&g_adst[d * 4];
    float e0 = __expf(lrelu(as.x + ad.x));
    float e1 = __expf(lrelu(as.y + ad.y));
    float e2 = __expf(lrelu(as.z + ad.z));
    float e3 = __expf(lrelu(as.w + ad.w));
    red4(&g_denom[d * 4], e0, e1, e2, e3);
}

// ---------------- K3: edge aggregation, head-reduced (64 floats/edge instead of 256) ----------------
__global__ void k_edge_agg(const void* __restrict__ ei) {
    int g = (blockIdx.x * 256 + threadIdx.x) >> 3;
    int lg = threadIdx.x & 7;
    if (g >= EE) return;
    int f = g_e64;
    int s = ldidx(ei, g, f, NN);
    int d = ldidx(ei, (long long)EE + g, f, NN);
    float4 as = *(const float4*)&g_asrc[s * 4];
    float4 ad = *(const float4*)&g_adst[d * 4];
    float4 dn = *(const float4*)&g_denom[d * 4];
    float al[4];
    al[0] = __fdividef(__expf(lrelu(as.x + ad.x)), dn.x);
    al[1] = __fdividef(__expf(lrelu(as.y + ad.y)), dn.y);
    al[2] = __fdividef(__expf(lrelu(as.z + ad.z)), dn.z);
    al[3] = __fdividef(__expf(lrelu(as.w + ad.w)), dn.w);
    float v[8] = {0.f, 0.f, 0.f, 0.f, 0.f, 0.f, 0.f, 0.f};
#pragma unroll
    for (int h = 0; h < 4; h++) {
        uint4 raw = *(const uint4*)&g_xp[(size_t)s * 256 + h * 64 + lg * 8];
        float2 p0 = bf2f(raw.x), p1 = bf2f(raw.y), p2 = bf2f(raw.z), p3 = bf2f(raw.w);
        float a = al[h];
        v[0] += a * p0.x; v[1] += a * p0.y; v[2] += a * p1.x; v[3] += a * p1.y;
        v[4] += a * p2.x; v[5] += a * p2.y; v[6] += a * p3.x; v[7] += a * p3.y;
    }
    float* dst = &g_out[(size_t)d * 64 + lg * 8];
    red4(dst, v[0], v[1], v[2], v[3]);
    red4(dst + 4, v[4], v[5], v[6], v[7]);
}

// ---------------- K4: node finalize (self-loop + head-mean + bias + relu) and graph pool ----------------
__global__ void k_node(const void* __restrict__ batch, const float* __restrict__ bias) {
    int n = (blockIdx.x * 256 + threadIdx.x) >> 3;
    int lg = threadIdx.x & 7;
    if (n >= NN) return;
    float4 se = *(const float4*)&g_selfex[n * 4];
    float4 dn = *(const float4*)&g_denom[n * 4];
    float al[4];
    al[0] = __fdividef(se.x, dn.x);
    al[1] = __fdividef(se.y, dn.y);
    al[2] = __fdividef(se.z, dn.z);
    al[3] = __fdividef(se.w, dn.w);
    float v[8] = {0.f, 0.f, 0.f, 0.f, 0.f, 0.f, 0.f, 0.f};
#pragma unroll
    for (int h = 0; h < 4; h++) {
        uint4 raw = *(const uint4*)&g_xp[(size_t)n * 256 + h * 64 + lg * 8];
        float2 p0 = bf2f(raw.x), p1 = bf2f(raw.y), p2 = bf2f(raw.z), p3 = bf2f(raw.w);
        float a = al[h];
        v[0] += a * p0.x; v[1] += a * p0.y; v[2] += a * p1.x; v[3] += a * p1.y;
        v[4] += a * p2.x; v[5] += a * p2.y; v[6] += a * p3.x; v[7] += a * p3.y;
    }
    float4 o0 = *(const float4*)&g_out[(size_t)n * 64 + lg * 8];
    float4 o1 = *(const float4*)&g_out[(size_t)n * 64 + lg * 8 + 4];
    float4 b0 = *(const float4*)&bias[lg * 8];
    float4 b1 = *(const float4*)&bias[lg * 8 + 4];
    float h0 = fmaxf((v[0] + o0.x) * 0.25f + b0.x, 0.f);
    float h1 = fmaxf((v[1] + o0.y) * 0.25f + b0.y, 0.f);
    float h2 = fmaxf((v[2] + o0.z) * 0.25f + b0.z, 0.f);
    float h3 = fmaxf((v[3] + o0.w) * 0.25f + b0.w, 0.f);
    float h4 = fmaxf((v[4] + o1.x) * 0.25f + b1.x, 0.f);
    float h5 = fmaxf((v[5] + o1.y) * 0.25f + b1.y, 0.f);
    float h6 = fmaxf((v[6] + o1.z) * 0.25f + b1.z, 0.f);
    float h7 = fmaxf((v[7] + o1.w) * 0.25f + b1.w, 0.f);
    int gph = ldidx(batch, n, g_b64, GG);
    float* dst = &g_pool[gph * 64 + lg * 8];
    red4(dst, h0, h1, h2, h3);
    red4(dst + 4, h4, h5, h6, h7);
    if (lg == 0) atomicAdd(&g_cnt[gph], 1.0f);
}

// ---------------- K5: per-graph mean + MLP head + sigmoid ----------------
__global__ void k_head(const float* __restrict__ w1, const float* __restrict__ b1,
                       const float* __restrict__ w2, const float* __restrict__ b2,
                       float* __restrict__ out) {
    __shared__ float w1s[64 * 64];
    __shared__ float b1s[64];
    __shared__ float w2s[64];
    int t = threadIdx.x;
    for (int i = t; i < 64 * 64; i += 128) w1s[i] = w1[i];
    if (t < 64) { b1s[t] = b1[t]; w2s[t] = w2[t]; }
    __syncthreads();
    if (t < GG) {
        float cnt = fmaxf(g_cnt[t], 1.0f);
        float inv = 1.0f / cnt;
        float gv[64];
#pragma unroll
        for (int c = 0; c < 64; c++) gv[c] = g_pool[t * 64 + c] * inv;
        float z = b2[0];
        for (int k = 0; k < 64; k++) {
            float a = b1s[k];
#pragma unroll
            for (int c = 0; c < 64; c++) a += gv[c] * w1s[c * 64 + k];
            a = fmaxf(a, 0.f);
            z += a * w2s[k];
        }
        out[t] = 1.0f / (1.0f + expf(-z));
    }
}

// ---------------- launcher ----------------
extern "C" void kernel_launch(void* const* d_in, const int* in_sizes, int n_in,
                              void* d_out, int out_size) {
    const float* x       = (const float*)d_in[0];
    const float* W       = (const float*)d_in[1];
    const float* att_src = (const float*)d_in[2];
    const float* att_dst = (const float*)d_in[3];
    const float* bias    = (const float*)d_in[4];
    const float* w1      = (const float*)d_in[5];
    const float* b1      = (const float*)d_in[6];
    const float* w2      = (const float*)d_in[7];
    const float* b2      = (const float*)d_in[8];
    const void*  ei      = d_in[9];
    const void*  bat     = d_in[10];

    k_detect<<<1, 256>>>((const int*)ei, (const int*)bat);
    k_zero<<<400, 256>>>();
    dim3 gg((NN + 127) / 128, 2);
    k_gemm<<<gg, 256>>>(x, W);
    k_attn<<<(NN * 32 + 255) / 256, 256>>>(att_src, att_dst);
    k_edge_denom<<<(EE + 255) / 256, 256>>>(ei);
    k_edge_agg<<<(int)(((long long)EE * 8 + 255) / 256), 256>>>(ei);
    k_node<<<(NN * 8 + 255) / 256, 256>>>(bat, bias);
    k_head<<<1, 128>>>(w1, b1, w2, b2, (float*)d_out);
}

// round 7
// speedup vs baseline: 1.3987x; 1.3987x over previous
#include <cuda_runtime.h>
#include <cuda_bf16.h>
#include <cstdint>

#define NN 100000
#define EE 1600000
#define GG 128
#define IND 329
#define NEG 0.2f

// ---------------- device scratch (no allocation allowed) ----------------
__device__ __align__(256) __nv_bfloat16 g_xp[(size_t)NN * 256];   // 51.2 MB bf16 features [N][H*C]
__device__ __align__(256) float g_asrc[NN * 4];
__device__ __align__(256) float g_adst[NN * 4];
__device__ __align__(256) float g_denom[NN * 4];
__device__ __align__(256) float g_selfex[NN * 4];
__device__ __align__(256) float g_out[(size_t)NN * 64];           // 25.6 MB head-summed aggregate
__device__ __align__(256) float g_pool[GG * 64];
__device__ __align__(256) float g_cnt[GG];
__device__ int g_e64;   // 1 if edge_index is int64, 0 if int32
__device__ int g_b64;   // 1 if batch is int64, 0 if int32

// ---------------- small helpers ----------------
__device__ __forceinline__ float2 bf2f(unsigned u) {
    __nv_bfloat162 b = *reinterpret_cast<const __nv_bfloat162*>(&u);
    return __bfloat1622float2(b);
}
__device__ __forceinline__ float lrelu(float x) { return x > 0.f ? x : NEG * x; }
__device__ __forceinline__ void red4(float* p, float a, float b, float c, float d) {
    asm volatile("red.global.add.v4.f32 [%0], {%1,%2,%3,%4};"
                 :: "l"(p), "f"(a), "f"(b), "f"(c), "f"(d) : "memory");
}
__device__ __forceinline__ unsigned f2tf32(float v) {
    unsigned u;
    asm("cvt.rna.tf32.f32 %0, %1;" : "=r"(u) : "f"(v));
    return u;
}
__device__ __forceinline__ void mma_tf32(float& c0, float& c1, float& c2, float& c3,
                                         unsigned a0, unsigned a1, unsigned a2, unsigned a3,
                                         unsigned b0, unsigned b1) {
    asm volatile("mma.sync.aligned.m16n8k8.row.col.f32.tf32.tf32.f32 "
                 "{%0,%1,%2,%3}, {%4,%5,%6,%7}, {%8,%9}, {%0,%1,%2,%3};"
                 : "+f"(c0), "+f"(c1), "+f"(c2), "+f"(c3)
                 : "r"(a0), "r"(a1), "r"(a2), "r"(a3), "r"(b0), "r"(b1));
}
// dtype-flexible index load, clamped to [0, lim-1]
__device__ __forceinline__ int ldidx(const void* p, long long i, int is64, int lim) {
    long long v = is64 ? ((const long long*)p)[i] : (long long)((const int*)p)[i];
    if (v < 0) v = 0;
    if (v >= lim) v = lim - 1;
    return (int)v;
}

// ---------------- K-1: dtype detector (int32 vs int64) ----------------
__global__ void k_detect(const int* __restrict__ ei_raw, const int* __restrict__ bat_raw) {
    __shared__ int nz_e, nz_b;
    int t = threadIdx.x;  // 256 threads
    if (t == 0) { nz_e = 0; nz_b = 0; }
    __syncthreads();
    if (ei_raw[2 * t + 1] != 0) atomicOr(&nz_e, 1);
    if (bat_raw[NN - 1 - 2 * t] != 0) atomicOr(&nz_b, 1);
    __syncthreads();
    if (t == 0) { g_e64 = nz_e ? 0 : 1; g_b64 = nz_b ? 0 : 1; }
}

// ---------------- K0: zero accumulators ----------------
__global__ void k_zero() {
    int i = blockIdx.x * blockDim.x + threadIdx.x;
    int stride = gridDim.x * blockDim.x;
    float4 z = make_float4(0.f, 0.f, 0.f, 0.f);
    float4* o = (float4*)g_out;
    for (int j = i; j < NN * 64 / 4; j += stride) o[j] = z;
    if (i < GG * 64 / 4) ((float4*)g_pool)[i] = z;
    if (i < GG / 4) ((float4*)g_cnt)[i] = z;
}

// ---------------- K1: TF32 tensor-core GEMM  xp = x @ W  (bf16 store) ----------------
// BM=128, BN=128, BK=16, 256 threads = 8 warps (4 along M x 2 along N),
// warp tile 32x64 = 2 m-tiles x 8 n-tiles of m16n8k8.
// Smem stride 136 makes all mma-fragment LDS conflict-free.
#define SSTRIDE 136
__global__ __launch_bounds__(256) void k_gemm(const float* __restrict__ x,
                                              const float* __restrict__ W) {
    __shared__ unsigned As[16][SSTRIDE];
    __shared__ unsigned Bs[16][SSTRIDE];
    int tid = threadIdx.x;
    int lane = tid & 31;
    int wid = tid >> 5;
    int warpM = wid & 3;          // 0..3 -> 32-row slabs
    int warpN = wid >> 2;         // 0..1 -> 64-col slabs
    int rowBase = blockIdx.x * 128;
    int colBase = blockIdx.y * 128;
    int p = lane >> 2;            // 0..7
    int q = lane & 3;             // 0..3

    float acc[2][8][4];
#pragma unroll
    for (int i = 0; i < 2; i++)
#pragma unroll
        for (int j = 0; j < 8; j++)
#pragma unroll
            for (int r = 0; r < 4; r++) acc[i][j][r] = 0.f;

    // A-load mapping: thread t -> row m=t>>1, k-offset (t&1)*8, 8 consecutive k
    int am = tid >> 1;
    int aklo = (tid & 1) * 8;
    int arow = rowBase + am;
    // B-load mapping: thread t -> k=t>>4, cols (t&15)*8 .. +7
    int bkk = tid >> 4;
    int bc = (tid & 15) * 8;

    for (int kt = 0; kt < 21; kt++) {
        int k0 = kt * 16;
        // load A tile (x is [NN][329] row-major, scalar loads)
        float av[8];
#pragma unroll
        for (int i = 0; i < 8; i++) {
            int kk = k0 + aklo + i;
            av[i] = (arow < NN && kk < IND) ? x[(size_t)arow * IND + kk] : 0.f;
        }
        // load B tile (W is [329][256] row-major, vectorized)
        float4 bv0 = make_float4(0.f, 0.f, 0.f, 0.f), bv1 = bv0;
        {
            int kk = k0 + bkk;
            if (kk < IND) {
                bv0 = *(const float4*)&W[(size_t)kk * 256 + colBase + bc];
                bv1 = *(const float4*)&W[(size_t)kk * 256 + colBase + bc + 4];
            }
        }
        __syncthreads();
#pragma unroll
        for (int i = 0; i < 8; i++) As[aklo + i][am] = f2tf32(av[i]);
        Bs[bkk][bc + 0] = f2tf32(bv0.x); Bs[bkk][bc + 1] = f2tf32(bv0.y);
        Bs[bkk][bc + 2] = f2tf32(bv0.z); Bs[bkk][bc + 3] = f2tf32(bv0.w);
        Bs[bkk][bc + 4] = f2tf32(bv1.x); Bs[bkk][bc + 5] = f2tf32(bv1.y);
        Bs[bkk][bc + 6] = f2tf32(bv1.z); Bs[bkk][bc + 7] = f2tf32(bv1.w);
        __syncthreads();

#pragma unroll
        for (int ks = 0; ks < 16; ks += 8) {
            unsigned a[2][4];
#pragma unroll
            for (int mt = 0; mt < 2; mt++) {
                int m0 = warpM * 32 + mt * 16;
                a[mt][0] = As[ks + q][m0 + p];
                a[mt][1] = As[ks + q][m0 + p + 8];
                a[mt][2] = As[ks + q + 4][m0 + p];
                a[mt][3] = As[ks + q + 4][m0 + p + 8];
            }
#pragma unroll
            for (int nt = 0; nt < 8; nt++) {
                int n0 = warpN * 64 + nt * 8;
                unsigned b0 = Bs[ks + q][n0 + p];
                unsigned b1 = Bs[ks + q + 4][n0 + p];
#pragma unroll
                for (int mt = 0; mt < 2; mt++)
                    mma_tf32(acc[mt][nt][0], acc[mt][nt][1], acc[mt][nt][2], acc[mt][nt][3],
                             a[mt][0], a[mt][1], a[mt][2], a[mt][3], b0, b1);
            }
        }
    }

    // epilogue: c0/c1 at (row = m0+p, col = n0+2q, +1); c2/c3 at row+8
#pragma unroll
    for (int mt = 0; mt < 2; mt++) {
        int r0 = rowBase + warpM * 32 + mt * 16 + p;
        int r1 = r0 + 8;
#pragma unroll
        for (int nt = 0; nt < 8; nt++) {
            int col = colBase + warpN * 64 + nt * 8 + 2 * q;
            if (r0 < NN) {
                __nv_bfloat162 v = __floats2bfloat162_rn(acc[mt][nt][0], acc[mt][nt][1]);
                *(__nv_bfloat162*)&g_xp[(size_t)r0 * 256 + col] = v;
            }
            if (r1 < NN) {
                __nv_bfloat162 v = __floats2bfloat162_rn(acc[mt][nt][2], acc[mt][nt][3]);
                *(__nv_bfloat162*)&g_xp[(size_t)r1 * 256 + col] = v;
            }
        }
    }
}

// ---------------- K1b: per-node attention scalars + self-loop softmax init ----------------
__global__ void k_attn(const float* __restrict__ att_src, const float* __restrict__ att_dst) {
    int w = (blockIdx.x * blockDim.x + threadIdx.x) >> 5;
    int lane = threadIdx.x & 31;
    if (w >= NN) return;
    float4 s0 = *(const float4*)&att_src[lane * 8];
    float4 s1 = *(const float4*)&att_src[lane * 8 + 4];
    float4 d0 = *(const float4*)&att_dst[lane * 8];
    float4 d1 = *(const float4*)&att_dst[lane * 8 + 4];
    uint4 raw = *(const uint4*)&g_xp[(size_t)w * 256 + lane * 8];
    float2 p0 = bf2f(raw.x), p1 = bf2f(raw.y), p2 = bf2f(raw.z), p3 = bf2f(raw.w);
    float sdot = p0.x * s0.x + p0.y * s0.y + p1.x * s0.z + p1.y * s0.w
               + p2.x * s1.x + p2.y * s1.y + p3.x * s1.z + p3.y * s1.w;
    float ddot = p0.x * d0.x + p0.y * d0.y + p1.x * d0.z + p1.y * d0.w
               + p2.x * d1.x + p2.y * d1.y + p3.x * d1.z + p3.y * d1.w;
#pragma unroll
    for (int off = 1; off < 8; off <<= 1) {
        sdot += __shfl_xor_sync(0xffffffffu, sdot, off);
        ddot += __shfl_xor_sync(0xffffffffu, ddot, off);
    }
    if ((lane & 7) == 0) {
        int h = lane >> 3;
        g_asrc[w * 4 + h] = sdot;
        g_adst[w * 4 + h] = ddot;
        float ex = __expf(lrelu(sdot + ddot));     // self-loop term
        g_selfex[w * 4 + h] = ex;
        g_denom[w * 4 + h] = ex;                   // denom init = self term
    }
}

// ---------------- K2: edge softmax denominator (max-subtraction is a provable no-op) ----------------
__global__ void k_edge_denom(const void* __restrict__ ei) {
    int e = blockIdx.x * 256 + threadIdx.x;
    if (e >= EE) return;
    int f = g_e64;
    int s = ldidx(ei, e, f, NN);
    int d = ldidx(ei, (long long)EE + e, f, NN);
    float4 as = *(const float4*)&g_asrc[s * 4];
    float4 ad = *(const float4*)&g_adst[d * 4];
    float e0 = __expf(lrelu(as.x + ad.x));
    float e1 = __expf(lrelu(as.y + ad.y));
    float e2 = __expf(lrelu(as.z + ad.z));
    float e3 = __expf(lrelu(as.w + ad.w));
    red4(&g_denom[d * 4], e0, e1, e2, e3);
}

// ---------------- K3: edge aggregation, head-reduced (64 floats/edge instead of 256) ----------------
__global__ void k_edge_agg(const void* __restrict__ ei) {
    int g = (blockIdx.x * 256 + threadIdx.x) >> 3;
    int lg = threadIdx.x & 7;
    if (g >= EE) return;
    int f = g_e64;
    int s = ldidx(ei, g, f, NN);
    int d = ldidx(ei, (long long)EE + g, f, NN);
    float4 as = *(const float4*)&g_asrc[s * 4];
    float4 ad = *(const float4*)&g_adst[d * 4];
    float4 dn = *(const float4*)&g_denom[d * 4];
    float al[4];
    al[0] = __fdividef(__expf(lrelu(as.x + ad.x)), dn.x);
    al[1] = __fdividef(__expf(lrelu(as.y + ad.y)), dn.y);
    al[2] = __fdividef(__expf(lrelu(as.z + ad.z)), dn.z);
    al[3] = __fdividef(__expf(lrelu(as.w + ad.w)), dn.w);
    float v[8] = {0.f, 0.f, 0.f, 0.f, 0.f, 0.f, 0.f, 0.f};
#pragma unroll
    for (int h = 0; h < 4; h++) {
        uint4 raw = *(const uint4*)&g_xp[(size_t)s * 256 + h * 64 + lg * 8];
        float2 p0 = bf2f(raw.x), p1 = bf2f(raw.y), p2 = bf2f(raw.z), p3 = bf2f(raw.w);
        float a = al[h];
        v[0] += a * p0.x; v[1] += a * p0.y; v[2] += a * p1.x; v[3] += a * p1.y;
        v[4] += a * p2.x; v[5] += a * p2.y; v[6] += a * p3.x; v[7] += a * p3.y;
    }
    float* dst = &g_out[(size_t)d * 64 + lg * 8];
    red4(dst, v[0], v[1], v[2], v[3]);
    red4(dst + 4, v[4], v[5], v[6], v[7]);
}

// ---------------- K4: node finalize (self-loop + head-mean + bias + relu) and graph pool ----------------
__global__ void k_node(const void* __restrict__ batch, const float* __restrict__ bias) {
    int n = (blockIdx.x * 256 + threadIdx.x) >> 3;
    int lg = threadIdx.x & 7;
    if (n >= NN) return;
    float4 se = *(const float4*)&g_selfex[n * 4];
    float4 dn = *(const float4*)&g_denom[n * 4];
    float al[4];
    al[0] = __fdividef(se.x, dn.x);
    al[1] = __fdividef(se.y, dn.y);
    al[2] = __fdividef(se.z, dn.z);
    al[3] = __fdividef(se.w, dn.w);
    float v[8] = {0.f, 0.f, 0.f, 0.f, 0.f, 0.f, 0.f, 0.f};
#pragma unroll
    for (int h = 0; h < 4; h++) {
        uint4 raw = *(const uint4*)&g_xp[(size_t)n * 256 + h * 64 + lg * 8];
        float2 p0 = bf2f(raw.x), p1 = bf2f(raw.y), p2 = bf2f(raw.z), p3 = bf2f(raw.w);
        float a = al[h];
        v[0] += a * p0.x; v[1] += a * p0.y; v[2] += a * p1.x; v[3] += a * p1.y;
        v[4] += a * p2.x; v[5] += a * p2.y; v[6] += a * p3.x; v[7] += a * p3.y;
    }
    float4 o0 = *(const float4*)&g_out[(size_t)n * 64 + lg * 8];
    float4 o1 = *(const float4*)&g_out[(size_t)n * 64 + lg * 8 + 4];
    float4 b0 = *(const float4*)&bias[lg * 8];
    float4 b1 = *(const float4*)&bias[lg * 8 + 4];
    float h0 = fmaxf((v[0] + o0.x) * 0.25f + b0.x, 0.f);
    float h1 = fmaxf((v[1] + o0.y) * 0.25f + b0.y, 0.f);
    float h2 = fmaxf((v[2] + o0.z) * 0.25f + b0.z, 0.f);
    float h3 = fmaxf((v[3] + o0.w) * 0.25f + b0.w, 0.f);
    float h4 = fmaxf((v[4] + o1.x) * 0.25f + b1.x, 0.f);
    float h5 = fmaxf((v[5] + o1.y) * 0.25f + b1.y, 0.f);
    float h6 = fmaxf((v[6] + o1.z) * 0.25f + b1.z, 0.f);
    float h7 = fmaxf((v[7] + o1.w) * 0.25f + b1.w, 0.f);
    int gph = ldidx(batch, n, g_b64, GG);
    float* dst = &g_pool[gph * 64 + lg * 8];
    red4(dst, h0, h1, h2, h3);
    red4(dst + 4, h4, h5, h6, h7);
    if (lg == 0) atomicAdd(&g_cnt[gph], 1.0f);
}

// ---------------- K5: per-graph mean + MLP head + sigmoid ----------------
__global__ void k_head(const float* __restrict__ w1, const float* __restrict__ b1,
                       const float* __restrict__ w2, const float* __restrict__ b2,
                       float* __restrict__ out) {
    __shared__ float w1s[64 * 64];
    __shared__ float b1s[64];
    __shared__ float w2s[64];
    int t = threadIdx.x;
    for (int i = t; i < 64 * 64; i += 128) w1s[i] = w1[i];
    if (t < 64) { b1s[t] = b1[t]; w2s[t] = w2[t]; }
    __syncthreads();
    if (t < GG) {
        float cnt = fmaxf(g_cnt[t], 1.0f);
        float inv = 1.0f / cnt;
        float gv[64];
#pragma unroll
        for (int c = 0; c < 64; c++) gv[c] = g_pool[t * 64 + c] * inv;
        float z = b2[0];
        for (int k = 0; k < 64; k++) {
            float a = b1s[k];
#pragma unroll
            for (int c = 0; c < 64; c++) a += gv[c] * w1s[c * 64 + k];
            a = fmaxf(a, 0.f);
            z += a * w2s[k];
        }
        out[t] = 1.0f / (1.0f + expf(-z));
    }
}

// ---------------- launcher ----------------
extern "C" void kernel_launch(void* const* d_in, const int* in_sizes, int n_in,
                              void* d_out, int out_size) {
    const float* x       = (const float*)d_in[0];
    const float* W       = (const float*)d_in[1];
    const float* att_src = (const float*)d_in[2];
    const float* att_dst = (const float*)d_in[3];
    const float* bias    = (const float*)d_in[4];
    const float* w1      = (const float*)d_in[5];
    const float* b1      = (const float*)d_in[6];
    const float* w2      = (const float*)d_in[7];
    const float* b2      = (const float*)d_in[8];
    const void*  ei      = d_in[9];
    const void*  bat     = d_in[10];

    k_detect<<<1, 256>>>((const int*)ei, (const int*)bat);
    k_zero<<<400, 256>>>();
    dim3 gg((NN + 127) / 128, 2);
    k_gemm<<<gg, 256>>>(x, W);
    k_attn<<<(NN * 32 + 255) / 256, 256>>>(att_src, att_dst);
    k_edge_denom<<<(EE + 255) / 256, 256>>>(ei);
    k_edge_agg<<<(int)(((long long)EE * 8 + 255) / 256), 256>>>(ei);
    k_node<<<(NN * 8 + 255) / 256, 256>>>(bat, bias);
    k_head<<<1, 128>>>(w1, b1, w2, b2, (float*)d_out);
}

// round 8
// speedup vs baseline: 1.4458x; 1.0337x over previous
#include <cuda_runtime.h>
#include <cuda_bf16.h>
#include <cstdint>

#define NN 100000
#define EE 1600000
#define GG 128
#define IND 329
#define NEG 0.2f

// ---------------- device scratch (no allocation allowed) ----------------
__device__ __align__(256) __nv_bfloat16 g_xp[(size_t)NN * 256];   // 51.2 MB bf16 features [N][H*C]
__device__ __align__(256) float g_asrc[NN * 4];
__device__ __align__(256) float g_adst[NN * 4];
__device__ __align__(256) float g_ex[(size_t)EE * 4];             // 25.6 MB per-edge exp values
__device__ __align__(256) int   g_srcs[EE];                       // 6.4 MB dst-binned src list
__device__ __align__(256) int   g_deg[NN];
__device__ __align__(256) int   g_off[NN + 1];
__device__ __align__(256) int   g_cursor[NN];
__device__ __align__(256) float g_pool[GG * 64];
__device__ __align__(256) float g_cnt[GG];
__device__ int g_e64;   // 1 if edge_index is int64, 0 if int32
__device__ int g_b64;   // 1 if batch is int64, 0 if int32

// ---------------- small helpers ----------------
__device__ __forceinline__ float2 bf2f(unsigned u) {
    __nv_bfloat162 b = *reinterpret_cast<const __nv_bfloat162*>(&u);
    return __bfloat1622float2(b);
}
__device__ __forceinline__ float lrelu(float x) { return x > 0.f ? x : NEG * x; }
__device__ __forceinline__ void red2(float* p, float a, float b) {
    asm volatile("red.global.add.v2.f32 [%0], {%1,%2};"
                 :: "l"(p), "f"(a), "f"(b) : "memory");
}
__device__ __forceinline__ unsigned f2tf32(float v) {
    unsigned u;
    asm("cvt.rna.tf32.f32 %0, %1;" : "=r"(u) : "f"(v));
    return u;
}
__device__ __forceinline__ void mma_tf32(float& c0, float& c1, float& c2, float& c3,
                                         unsigned a0, unsigned a1, unsigned a2, unsigned a3,
                                         unsigned b0, unsigned b1) {
    asm volatile("mma.sync.aligned.m16n8k8.row.col.f32.tf32.tf32.f32 "
                 "{%0,%1,%2,%3}, {%4,%5,%6,%7}, {%8,%9}, {%0,%1,%2,%3};"
                 : "+f"(c0), "+f"(c1), "+f"(c2), "+f"(c3)
                 : "r"(a0), "r"(a1), "r"(a2), "r"(a3), "r"(b0), "r"(b1));
}
// dtype-flexible index load, clamped to [0, lim-1]
__device__ __forceinline__ int ldidx(const void* p, long long i, int is64, int lim) {
    long long v = is64 ? ((const long long*)p)[i] : (long long)((const int*)p)[i];
    if (v < 0) v = 0;
    if (v >= lim) v = lim - 1;
    return (int)v;
}

// ---------------- K-1: dtype detector (int32 vs int64) ----------------
__global__ void k_detect(const int* __restrict__ ei_raw, const int* __restrict__ bat_raw) {
    __shared__ int nz_e, nz_b;
    int t = threadIdx.x;  // 256 threads
    if (t == 0) { nz_e = 0; nz_b = 0; }
    __syncthreads();
    if (ei_raw[2 * t + 1] != 0) atomicOr(&nz_e, 1);
    if (bat_raw[NN - 1 - 2 * t] != 0) atomicOr(&nz_b, 1);
    __syncthreads();
    if (t == 0) { g_e64 = nz_e ? 0 : 1; g_b64 = nz_b ? 0 : 1; }
}

// ---------------- K0: zero degree table + pool accumulators ----------------
__global__ void k_zero() {
    int i = blockIdx.x * blockDim.x + threadIdx.x;
    int stride = gridDim.x * blockDim.x;
    for (int j = i; j < NN; j += stride) g_deg[j] = 0;
    if (i < GG * 64) g_pool[i] = 0.f;
    if (i < GG) g_cnt[i] = 0.f;
}

// ---------------- CSR build: histogram ----------------
__global__ void k_hist(const void* __restrict__ ei) {
    int e = blockIdx.x * 256 + threadIdx.x;
    if (e >= EE) return;
    int d = ldidx(ei, (long long)EE + e, g_e64, NN);
    atomicAdd(&g_deg[d], 1);
}

// ---------------- CSR build: single-block exclusive scan (4 elems/thread) ----------------
__global__ __launch_bounds__(1024) void k_scan() {
    __shared__ int wsum[32];
    __shared__ int s_carry, s_tot;
    int tid = threadIdx.x, lane = tid & 31, wid = tid >> 5;
    if (tid == 0) s_carry = 0;
    __syncthreads();
    for (int base = 0; base < NN; base += 4096) {
        int idx = base + tid * 4;
        int v[4];
        int sum = 0;
#pragma unroll
        for (int i = 0; i < 4; i++) {
            v[i] = (idx + i < NN) ? g_deg[idx + i] : 0;
            sum += v[i];
        }
        int inc = sum;
#pragma unroll
        for (int off = 1; off < 32; off <<= 1) {
            int t = __shfl_up_sync(0xffffffffu, inc, off);
            if (lane >= off) inc += t;
        }
        if (lane == 31) wsum[wid] = inc;
        __syncthreads();
        if (wid == 0) {
            int x = wsum[lane];
            int iw = x;
#pragma unroll
            for (int off = 1; off < 32; off <<= 1) {
                int t = __shfl_up_sync(0xffffffffu, iw, off);
                if (lane >= off) iw += t;
            }
            if (lane == 31) s_tot = iw;
            wsum[lane] = iw - x;
        }
        __syncthreads();
        int run = s_carry + wsum[wid] + (inc - sum);
#pragma unroll
        for (int i = 0; i < 4; i++) {
            if (idx + i < NN) { g_off[idx + i] = run; g_cursor[idx + i] = run; }
            run += v[i];
        }
        __syncthreads();
        if (tid == 0) s_carry += s_tot;
        __syncthreads();
    }
    if (tid == 0) g_off[NN] = EE;
}

// ---------------- CSR build: scatter srcs into dst bins ----------------
__global__ void k_scatter(const void* __restrict__ ei) {
    int e = blockIdx.x * 256 + threadIdx.x;
    if (e >= EE) return;
    int f = g_e64;
    int s = ldidx(ei, e, f, NN);
    int d = ldidx(ei, (long long)EE + e, f, NN);
    int p = atomicAdd(&g_cursor[d], 1);
    g_srcs[p] = s;
}

// ---------------- K1: TF32 tensor-core GEMM  xp = x @ W  (bf16 store) ----------------
#define SSTRIDE 136
__global__ __launch_bounds__(256) void k_gemm(const float* __restrict__ x,
                                              const float* __restrict__ W) {
    __shared__ unsigned As[16][SSTRIDE];
    __shared__ unsigned Bs[16][SSTRIDE];
    int tid = threadIdx.x;
    int lane = tid & 31;
    int wid = tid >> 5;
    int warpM = wid & 3;
    int warpN = wid >> 2;
    int rowBase = blockIdx.x * 128;
    int colBase = blockIdx.y * 128;
    int p = lane >> 2;
    int q = lane & 3;

    float acc[2][8][4];
#pragma unroll
    for (int i = 0; i < 2; i++)
#pragma unroll
        for (int j = 0; j < 8; j++)
#pragma unroll
            for (int r = 0; r < 4; r++) acc[i][j][r] = 0.f;

    int am = tid >> 1;
    int aklo = (tid & 1) * 8;
    int arow = rowBase + am;
    int bkk = tid >> 4;
    int bc = (tid & 15) * 8;

    for (int kt = 0; kt < 21; kt++) {
        int k0 = kt * 16;
        float av[8];
#pragma unroll
        for (int i = 0; i < 8; i++) {
            int kk = k0 + aklo + i;
            av[i] = (arow < NN && kk < IND) ? x[(size_t)arow * IND + kk] : 0.f;
        }
        float4 bv0 = make_float4(0.f, 0.f, 0.f, 0.f), bv1 = bv0;
        {
            int kk = k0 + bkk;
            if (kk < IND) {
                bv0 = *(const float4*)&W[(size_t)kk * 256 + colBase + bc];
                bv1 = *(const float4*)&W[(size_t)kk * 256 + colBase + bc + 4];
            }
        }
        __syncthreads();
#pragma unroll
        for (int i = 0; i < 8; i++) As[aklo + i][am] = f2tf32(av[i]);
        Bs[bkk][bc + 0] = f2tf32(bv0.x); Bs[bkk][bc + 1] = f2tf32(bv0.y);
        Bs[bkk][bc + 2] = f2tf32(bv0.z); Bs[bkk][bc + 3] = f2tf32(bv0.w);
        Bs[bkk][bc + 4] = f2tf32(bv1.x); Bs[bkk][bc + 5] = f2tf32(bv1.y);
        Bs[bkk][bc + 6] = f2tf32(bv1.z); Bs[bkk][bc + 7] = f2tf32(bv1.w);
        __syncthreads();

#pragma unroll
        for (int ks = 0; ks < 16; ks += 8) {
            unsigned a[2][4];
#pragma unroll
            for (int mt = 0; mt < 2; mt++) {
                int m0 = warpM * 32 + mt * 16;
                a[mt][0] = As[ks + q][m0 + p];
                a[mt][1] = As[ks + q][m0 + p + 8];
                a[mt][2] = As[ks + q + 4][m0 + p];
                a[mt][3] = As[ks + q + 4][m0 + p + 8];
            }
#pragma unroll
            for (int nt = 0; nt < 8; nt++) {
                int n0 = warpN * 64 + nt * 8;
                unsigned b0 = Bs[ks + q][n0 + p];
                unsigned b1 = Bs[ks + q + 4][n0 + p];
#pragma unroll
                for (int mt = 0; mt < 2; mt++)
                    mma_tf32(acc[mt][nt][0], acc[mt][nt][1], acc[mt][nt][2], acc[mt][nt][3],
                             a[mt][0], a[mt][1], a[mt][2], a[mt][3], b0, b1);
            }
        }
    }

#pragma unroll
    for (int mt = 0; mt < 2; mt++) {
        int r0 = rowBase + warpM * 32 + mt * 16 + p;
        int r1 = r0 + 8;
#pragma unroll
        for (int nt = 0; nt < 8; nt++) {
            int col = colBase + warpN * 64 + nt * 8 + 2 * q;
            if (r0 < NN) {
                __nv_bfloat162 v = __floats2bfloat162_rn(acc[mt][nt][0], acc[mt][nt][1]);
                *(__nv_bfloat162*)&g_xp[(size_t)r0 * 256 + col] = v;
            }
            if (r1 < NN) {
                __nv_bfloat162 v = __floats2bfloat162_rn(acc[mt][nt][2], acc[mt][nt][3]);
                *(__nv_bfloat162*)&g_xp[(size_t)r1 * 256 + col] = v;
            }
        }
    }
}

// ---------------- K1b: per-node attention scalars ----------------
__global__ void k_attn(const float* __restrict__ att_src, const float* __restrict__ att_dst) {
    int w = (blockIdx.x * blockDim.x + threadIdx.x) >> 5;
    int lane = threadIdx.x & 31;
    if (w >= NN) return;
    float4 s0 = *(const float4*)&att_src[lane * 8];
    float4 s1 = *(const float4*)&att_src[lane * 8 + 4];
    float4 d0 = *(const float4*)&att_dst[lane * 8];
    float4 d1 = *(const float4*)&att_dst[lane * 8 + 4];
    uint4 raw = *(const uint4*)&g_xp[(size_t)w * 256 + lane * 8];
    float2 p0 = bf2f(raw.x), p1 = bf2f(raw.y), p2 = bf2f(raw.z), p3 = bf2f(raw.w);
    float sdot = p0.x * s0.x + p0.y * s0.y + p1.x * s0.z + p1.y * s0.w
               + p2.x * s1.x + p2.y * s1.y + p3.x * s1.z + p3.y * s1.w;
    float ddot = p0.x * d0.x + p0.y * d0.y + p1.x * d0.z + p1.y * d0.w
               + p2.x * d1.x + p2.y * d1.y + p3.x * d1.z + p3.y * d1.w;
#pragma unroll
    for (int off = 1; off < 8; off <<= 1) {
        sdot += __shfl_xor_sync(0xffffffffu, sdot, off);
        ddot += __shfl_xor_sync(0xffffffffu, ddot, off);
    }
    if ((lane & 7) == 0) {
        int h = lane >> 3;
        g_asrc[w * 4 + h] = sdot;
        g_adst[w * 4 + h] = ddot;
    }
}

// ---------------- K3: fused per-node softmax + aggregation + finalize + pool ----------------
// one warp per node; lane covers output cols (lane*2, lane*2+1)
__global__ __launch_bounds__(256) void k_node_csr(const void* __restrict__ batch,
                                                  const float* __restrict__ bias) {
    int n = (blockIdx.x * 256 + threadIdx.x) >> 5;
    int lane = threadIdx.x & 31;
    if (n >= NN) return;
    float4 ad = *(const float4*)&g_adst[n * 4];
    float4 an = *(const float4*)&g_asrc[n * 4];
    // self-loop exp
    float se0 = __expf(lrelu(an.x + ad.x));
    float se1 = __expf(lrelu(an.y + ad.y));
    float se2 = __expf(lrelu(an.z + ad.z));
    float se3 = __expf(lrelu(an.w + ad.w));
    int o0 = g_off[n], o1 = g_off[n + 1];

    // loop1: compute per-edge exps (stored), accumulate denominator
    float d0 = 0.f, d1 = 0.f, d2 = 0.f, d3 = 0.f;
    for (int e = o0 + lane; e < o1; e += 32) {
        int s = g_srcs[e];
        float4 as = *(const float4*)&g_asrc[s * 4];
        float e0 = __expf(lrelu(as.x + ad.x));
        float e1 = __expf(lrelu(as.y + ad.y));
        float e2 = __expf(lrelu(as.z + ad.z));
        float e3 = __expf(lrelu(as.w + ad.w));
        *(float4*)&g_ex[(size_t)e * 4] = make_float4(e0, e1, e2, e3);
        d0 += e0; d1 += e1; d2 += e2; d3 += e3;
    }
#pragma unroll
    for (int off = 16; off > 0; off >>= 1) {
        d0 += __shfl_xor_sync(0xffffffffu, d0, off);
        d1 += __shfl_xor_sync(0xffffffffu, d1, off);
        d2 += __shfl_xor_sync(0xffffffffu, d2, off);
        d3 += __shfl_xor_sync(0xffffffffu, d3, off);
    }
    float inv0 = __frcp_rn(d0 + se0);
    float inv1 = __frcp_rn(d1 + se1);
    float inv2 = __frcp_rn(d2 + se2);
    float inv3 = __frcp_rn(d3 + se3);

    int col = lane * 2;
    float acc0 = 0.f, acc1 = 0.f;
    // self-loop contribution
    {
        float a0 = se0 * inv0, a1 = se1 * inv1, a2 = se2 * inv2, a3 = se3 * inv3;
        const __nv_bfloat16* row = &g_xp[(size_t)n * 256];
        float2 p;
        p = bf2f(*(const unsigned*)&row[col]);        acc0 += a0 * p.x; acc1 += a0 * p.y;
        p = bf2f(*(const unsigned*)&row[64 + col]);   acc0 += a1 * p.x; acc1 += a1 * p.y;
        p = bf2f(*(const unsigned*)&row[128 + col]);  acc0 += a2 * p.x; acc1 += a2 * p.y;
        p = bf2f(*(const unsigned*)&row[192 + col]);  acc0 += a3 * p.x; acc1 += a3 * p.y;
    }
    // loop2: whole-warp per edge, coalesced xp gathers
    for (int e = o0; e < o1; e++) {
        int s = g_srcs[e];                                // broadcast
        float4 ex = *(const float4*)&g_ex[(size_t)e * 4]; // broadcast
        float a0 = ex.x * inv0, a1 = ex.y * inv1, a2 = ex.z * inv2, a3 = ex.w * inv3;
        const __nv_bfloat16* row = &g_xp[(size_t)s * 256];
        float2 p;
        p = bf2f(*(const unsigned*)&row[col]);        acc0 += a0 * p.x; acc1 += a0 * p.y;
        p = bf2f(*(const unsigned*)&row[64 + col]);   acc0 += a1 * p.x; acc1 += a1 * p.y;
        p = bf2f(*(const unsigned*)&row[128 + col]);  acc0 += a2 * p.x; acc1 += a2 * p.y;
        p = bf2f(*(const unsigned*)&row[192 + col]);  acc0 += a3 * p.x; acc1 += a3 * p.y;
    }
    // head mean + bias + relu
    float r0 = fmaxf(acc0 * 0.25f + bias[col], 0.f);
    float r1 = fmaxf(acc1 * 0.25f + bias[col + 1], 0.f);
    int gph = ldidx(batch, n, g_b64, GG);
    red2(&g_pool[gph * 64 + col], r0, r1);
    if (lane == 0) atomicAdd(&g_cnt[gph], 1.0f);
}

// ---------------- K5: per-graph mean + MLP head + sigmoid ----------------
__global__ void k_head(const float* __restrict__ w1, const float* __restrict__ b1,
                       const float* __restrict__ w2, const float* __restrict__ b2,
                       float* __restrict__ out) {
    __shared__ float w1s[64 * 64];
    __shared__ float b1s[64];
    __shared__ float w2s[64];
    int t = threadIdx.x;
    for (int i = t; i < 64 * 64; i += 128) w1s[i] = w1[i];
    if (t < 64) { b1s[t] = b1[t]; w2s[t] = w2[t]; }
    __syncthreads();
    if (t < GG) {
        float cnt = fmaxf(g_cnt[t], 1.0f);
        float inv = 1.0f / cnt;
        float gv[64];
#pragma unroll
        for (int c = 0; c < 64; c++) gv[c] = g_pool[t * 64 + c] * inv;
        float z = b2[0];
        for (int k = 0; k < 64; k++) {
            float a = b1s[k];
#pragma unroll
            for (int c = 0; c < 64; c++) a += gv[c] * w1s[c * 64 + k];
            a = fmaxf(a, 0.f);
            z += a * w2s[k];
        }
        out[t] = 1.0f / (1.0f + expf(-z));
    }
}

// ---------------- launcher ----------------
extern "C" void kernel_launch(void* const* d_in, const int* in_sizes, int n_in,
                              void* d_out, int out_size) {
    const float* x       = (const float*)d_in[0];
    const float* W       = (const float*)d_in[1];
    const float* att_src = (const float*)d_in[2];
    const float* att_dst = (const float*)d_in[3];
    const float* bias    = (const float*)d_in[4];
    const float* w1      = (const float*)d_in[5];
    const float* b1      = (const float*)d_in[6];
    const float* w2      = (const float*)d_in[7];
    const float* b2      = (const float*)d_in[8];
    const void*  ei      = d_in[9];
    const void*  bat     = d_in[10];

    k_detect<<<1, 256>>>((const int*)ei, (const int*)bat);
    k_zero<<<200, 512>>>();
    k_hist<<<(EE + 255) / 256, 256>>>(ei);
    k_scan<<<1, 1024>>>();
    k_scatter<<<(EE + 255) / 256, 256>>>(ei);
    dim3 gg((NN + 127) / 128, 2);
    k_gemm<<<gg, 256>>>(x, W);
    k_attn<<<(NN * 32 + 255) / 256, 256>>>(att_src, att_dst);
    k_node_csr<<<(NN * 32 + 255) / 256, 256>>>(bat, bias);
    k_head<<<1, 128>>>(w1, b1, w2, b2, (float*)d_out);
}

// round 9
// speedup vs baseline: 1.6513x; 1.1421x over previous
#include <cuda_runtime.h>
#include <cuda_bf16.h>
#include <cstdint>

#define NN 100000
#define EE 1600000
#define GG 128
#define IND 329
#define NEG 0.2f
#define NB 98          // ceil(NN/1024)

// ---------------- device scratch (no allocation allowed) ----------------
__device__ __align__(256) __nv_bfloat16 g_xp[(size_t)NN * 256];   // 51.2 MB bf16 features [N][H*C]
__device__ __align__(256) float g_asrc[NN * 4];
__device__ __align__(256) float g_adst[NN * 4];
__device__ __align__(256) float g_ex[(size_t)EE * 4];             // 25.6 MB per-edge exp values
__device__ __align__(256) int   g_srcs[EE];                       // 6.4 MB dst-binned src list
__device__ __align__(256) int   g_deg[NN];
__device__ __align__(256) int   g_off[NN + 1];
__device__ __align__(256) int   g_cursor[NN];
__device__ __align__(256) int   g_bsum[NB];
__device__ __align__(256) int   g_bsum2[NB];
__device__ __align__(256) float g_pool[GG * 64];
__device__ __align__(256) float g_cnt[GG];
__device__ int g_e64;   // 1 if edge_index is int64, 0 if int32
__device__ int g_b64;   // 1 if batch is int64, 0 if int32

// ---------------- small helpers ----------------
__device__ __forceinline__ float2 bf2f(unsigned u) {
    __nv_bfloat162 b = *reinterpret_cast<const __nv_bfloat162*>(&u);
    return __bfloat1622float2(b);
}
__device__ __forceinline__ float lrelu(float x) { return x > 0.f ? x : NEG * x; }
__device__ __forceinline__ void red2(float* p, float a, float b) {
    asm volatile("red.global.add.v2.f32 [%0], {%1,%2};"
                 :: "l"(p), "f"(a), "f"(b) : "memory");
}
__device__ __forceinline__ unsigned f2tf32(float v) {
    unsigned u;
    asm("cvt.rna.tf32.f32 %0, %1;" : "=r"(u) : "f"(v));
    return u;
}
__device__ __forceinline__ void mma_tf32(float& c0, float& c1, float& c2, float& c3,
                                         unsigned a0, unsigned a1, unsigned a2, unsigned a3,
                                         unsigned b0, unsigned b1) {
    asm volatile("mma.sync.aligned.m16n8k8.row.col.f32.tf32.tf32.f32 "
                 "{%0,%1,%2,%3}, {%4,%5,%6,%7}, {%8,%9}, {%0,%1,%2,%3};"
                 : "+f"(c0), "+f"(c1), "+f"(c2), "+f"(c3)
                 : "r"(a0), "r"(a1), "r"(a2), "r"(a3), "r"(b0), "r"(b1));
}
// dtype-flexible index load, clamped to [0, lim-1]
__device__ __forceinline__ int ldidx(const void* p, long long i, int is64, int lim) {
    long long v = is64 ? ((const long long*)p)[i] : (long long)((const int*)p)[i];
    if (v < 0) v = 0;
    if (v >= lim) v = lim - 1;
    return (int)v;
}

// ---------------- K-1: dtype detector (int32 vs int64) ----------------
__global__ void k_detect(const int* __restrict__ ei_raw, const int* __restrict__ bat_raw) {
    __shared__ int nz_e, nz_b;
    int t = threadIdx.x;  // 256 threads
    if (t == 0) { nz_e = 0; nz_b = 0; }
    __syncthreads();
    if (ei_raw[2 * t + 1] != 0) atomicOr(&nz_e, 1);
    if (bat_raw[NN - 1 - 2 * t] != 0) atomicOr(&nz_b, 1);
    __syncthreads();
    if (t == 0) { g_e64 = nz_e ? 0 : 1; g_b64 = nz_b ? 0 : 1; }
}

// ---------------- K0: zero degree table + pool accumulators ----------------
__global__ void k_zero() {
    int i = blockIdx.x * blockDim.x + threadIdx.x;
    int stride = gridDim.x * blockDim.x;
    for (int j = i; j < NN; j += stride) g_deg[j] = 0;
    if (i < GG * 64) g_pool[i] = 0.f;
    if (i < GG) g_cnt[i] = 0.f;
}

// ---------------- CSR build: histogram ----------------
__global__ void k_hist(const void* __restrict__ ei) {
    int e = blockIdx.x * 256 + threadIdx.x;
    if (e >= EE) return;
    int d = ldidx(ei, (long long)EE + e, g_e64, NN);
    atomicAdd(&g_deg[d], 1);
}

// ---------------- CSR build: 3-phase multi-block exclusive scan ----------------
__global__ __launch_bounds__(1024) void k_scanA() {
    __shared__ int wsum[32];
    int b = blockIdx.x, tid = threadIdx.x;
    int lane = tid & 31, wid = tid >> 5;
    int idx = b * 1024 + tid;
    int v = (idx < NN) ? g_deg[idx] : 0;
    int inc = v;
#pragma unroll
    for (int off = 1; off < 32; off <<= 1) {
        int t = __shfl_up_sync(0xffffffffu, inc, off);
        if (lane >= off) inc += t;
    }
    if (lane == 31) wsum[wid] = inc;
    __syncthreads();
    if (wid == 0) {
        int x = wsum[lane];
        int iw = x;
#pragma unroll
        for (int off = 1; off < 32; off <<= 1) {
            int t = __shfl_up_sync(0xffffffffu, iw, off);
            if (lane >= off) iw += t;
        }
        wsum[lane] = iw - x;   // exclusive warp offset
    }
    __syncthreads();
    int excl = inc - v + wsum[wid];
    if (idx < NN) g_off[idx] = excl;         // block-local exclusive
    if (tid == 1023) g_bsum[b] = excl + v;   // block total
}

__global__ void k_scanB() {
    __shared__ int wsum[4];
    int t = threadIdx.x;   // 128 threads
    int lane = t & 31, wid = t >> 5;
    int v = (t < NB) ? g_bsum[t] : 0;
    int inc = v;
#pragma unroll
    for (int off = 1; off < 32; off <<= 1) {
        int x = __shfl_up_sync(0xffffffffu, inc, off);
        if (lane >= off) inc += x;
    }
    if (lane == 31) wsum[wid] = inc;
    __syncthreads();
    if (t == 0) {
        int run = 0;
#pragma unroll
        for (int i = 0; i < 4; i++) { int x = wsum[i]; wsum[i] = run; run += x; }
    }
    __syncthreads();
    if (t < NB) g_bsum2[t] = inc - v + wsum[wid];
}

__global__ __launch_bounds__(1024) void k_scanC() {
    int b = blockIdx.x, tid = threadIdx.x;
    int idx = b * 1024 + tid;
    if (idx < NN) {
        int o = g_off[idx] + g_bsum2[b];
        g_off[idx] = o;
        g_cursor[idx] = o;
    }
    if (idx == 0) g_off[NN] = EE;
}

// ---------------- CSR build: scatter srcs into dst bins ----------------
__global__ void k_scatter(const void* __restrict__ ei) {
    int e = blockIdx.x * 256 + threadIdx.x;
    if (e >= EE) return;
    int f = g_e64;
    int s = ldidx(ei, e, f, NN);
    int d = ldidx(ei, (long long)EE + e, f, NN);
    int p = atomicAdd(&g_cursor[d], 1);
    g_srcs[p] = s;
}

// ---------------- K1: TF32 tensor-core GEMM  xp = x @ W  (bf16 store)
//                  + fused attention dots a_src/a_dst from fp32 accumulators ----------------
#define SSTRIDE 136
__global__ __launch_bounds__(256) void k_gemm(const float* __restrict__ x,
                                              const float* __restrict__ W,
                                              const float* __restrict__ att_src,
                                              const float* __restrict__ att_dst) {
    __shared__ unsigned As[16][SSTRIDE];
    __shared__ unsigned Bs[16][SSTRIDE];
    int tid = threadIdx.x;
    int lane = tid & 31;
    int wid = tid >> 5;
    int warpM = wid & 3;
    int warpN = wid >> 2;
    int rowBase = blockIdx.x * 128;
    int colBase = blockIdx.y * 128;
    int p = lane >> 2;
    int q = lane & 3;

    float acc[2][8][4];
#pragma unroll
    for (int i = 0; i < 2; i++)
#pragma unroll
        for (int j = 0; j < 8; j++)
#pragma unroll
            for (int r = 0; r < 4; r++) acc[i][j][r] = 0.f;

    int am = tid >> 1;
    int aklo = (tid & 1) * 8;
    int arow = rowBase + am;
    int bkk = tid >> 4;
    int bc = (tid & 15) * 8;

    for (int kt = 0; kt < 21; kt++) {
        int k0 = kt * 16;
        float av[8];
#pragma unroll
        for (int i = 0; i < 8; i++) {
            int kk = k0 + aklo + i;
            av[i] = (arow < NN && kk < IND) ? x[(size_t)arow * IND + kk] : 0.f;
        }
        float4 bv0 = make_float4(0.f, 0.f, 0.f, 0.f), bv1 = bv0;
        {
            int kk = k0 + bkk;
            if (kk < IND) {
                bv0 = *(const float4*)&W[(size_t)kk * 256 + colBase + bc];
                bv1 = *(const float4*)&W[(size_t)kk * 256 + colBase + bc + 4];
            }
        }
        __syncthreads();
#pragma unroll
        for (int i = 0; i < 8; i++) As[aklo + i][am] = f2tf32(av[i]);
        Bs[bkk][bc + 0] = f2tf32(bv0.x); Bs[bkk][bc + 1] = f2tf32(bv0.y);
        Bs[bkk][bc + 2] = f2tf32(bv0.z); Bs[bkk][bc + 3] = f2tf32(bv0.w);
        Bs[bkk][bc + 4] = f2tf32(bv1.x); Bs[bkk][bc + 5] = f2tf32(bv1.y);
        Bs[bkk][bc + 6] = f2tf32(bv1.z); Bs[bkk][bc + 7] = f2tf32(bv1.w);
        __syncthreads();

#pragma unroll
        for (int ks = 0; ks < 16; ks += 8) {
            unsigned a[2][4];
#pragma unroll
            for (int mt = 0; mt < 2; mt++) {
                int m0 = warpM * 32 + mt * 16;
                a[mt][0] = As[ks + q][m0 + p];
                a[mt][1] = As[ks + q][m0 + p + 8];
                a[mt][2] = As[ks + q + 4][m0 + p];
                a[mt][3] = As[ks + q + 4][m0 + p + 8];
            }
#pragma unroll
            for (int nt = 0; nt < 8; nt++) {
                int n0 = warpN * 64 + nt * 8;
                unsigned b0 = Bs[ks + q][n0 + p];
                unsigned b1 = Bs[ks + q + 4][n0 + p];
#pragma unroll
                for (int mt = 0; mt < 2; mt++)
                    mma_tf32(acc[mt][nt][0], acc[mt][nt][1], acc[mt][nt][2], acc[mt][nt][3],
                             a[mt][0], a[mt][1], a[mt][2], a[mt][3], b0, b1);
            }
        }
    }

    // bf16 store epilogue
#pragma unroll
    for (int mt = 0; mt < 2; mt++) {
        int r0 = rowBase + warpM * 32 + mt * 16 + p;
        int r1 = r0 + 8;
#pragma unroll
        for (int nt = 0; nt < 8; nt++) {
            int col = colBase + warpN * 64 + nt * 8 + 2 * q;
            if (r0 < NN) {
                __nv_bfloat162 v = __floats2bfloat162_rn(acc[mt][nt][0], acc[mt][nt][1]);
                *(__nv_bfloat162*)&g_xp[(size_t)r0 * 256 + col] = v;
            }
            if (r1 < NN) {
                __nv_bfloat162 v = __floats2bfloat162_rn(acc[mt][nt][2], acc[mt][nt][3]);
                *(__nv_bfloat162*)&g_xp[(size_t)r1 * 256 + col] = v;
            }
        }
    }

    // fused attention dots: this warp's 64-col slab is exactly head h;
    // each (row, head) has exactly one owner quad -> plain stores, no atomics.
    int h = blockIdx.y * 2 + warpN;
    float a_s0[8], a_s1[8], a_d0[8], a_d1[8];
#pragma unroll
    for (int nt = 0; nt < 8; nt++) {
        int cb = h * 64 + nt * 8 + 2 * q;
        a_s0[nt] = att_src[cb]; a_s1[nt] = att_src[cb + 1];
        a_d0[nt] = att_dst[cb]; a_d1[nt] = att_dst[cb + 1];
    }
#pragma unroll
    for (int mt = 0; mt < 2; mt++) {
        float sdA = 0.f, ddA = 0.f, sdB = 0.f, ddB = 0.f;
#pragma unroll
        for (int nt = 0; nt < 8; nt++) {
            sdA += acc[mt][nt][0] * a_s0[nt] + acc[mt][nt][1] * a_s1[nt];
            ddA += acc[mt][nt][0] * a_d0[nt] + acc[mt][nt][1] * a_d1[nt];
            sdB += acc[mt][nt][2] * a_s0[nt] + acc[mt][nt][3] * a_s1[nt];
            ddB += acc[mt][nt][2] * a_d0[nt] + acc[mt][nt][3] * a_d1[nt];
        }
#pragma unroll
        for (int off = 1; off < 4; off <<= 1) {
            sdA += __shfl_xor_sync(0xffffffffu, sdA, off);
            ddA += __shfl_xor_sync(0xffffffffu, ddA, off);
            sdB += __shfl_xor_sync(0xffffffffu, sdB, off);
            ddB += __shfl_xor_sync(0xffffffffu, ddB, off);
        }
        if (q == 0) {
            int rA = rowBase + warpM * 32 + mt * 16 + p;
            int rB = rA + 8;
            if (rA < NN) { g_asrc[rA * 4 + h] = sdA; g_adst[rA * 4 + h] = ddA; }
            if (rB < NN) { g_asrc[rB * 4 + h] = sdB; g_adst[rB * 4 + h] = ddB; }
        }
    }
}

// ---------------- K3: fused per-node softmax + aggregation + finalize + pool ----------------
// one warp per node; lane covers output cols (lane*2, lane*2+1)
__global__ __launch_bounds__(256) void k_node_csr(const void* __restrict__ batch,
                                                  const float* __restrict__ bias) {
    int n = (blockIdx.x * 256 + threadIdx.x) >> 5;
    int lane = threadIdx.x & 31;
    if (n >= NN) return;
    float4 ad = *(const float4*)&g_adst[n * 4];
    float4 an = *(const float4*)&g_asrc[n * 4];
    float se0 = __expf(lrelu(an.x + ad.x));
    float se1 = __expf(lrelu(an.y + ad.y));
    float se2 = __expf(lrelu(an.z + ad.z));
    float se3 = __expf(lrelu(an.w + ad.w));
    int o0 = g_off[n], o1 = g_off[n + 1];

    // loop1: per-edge exps (stored) + denominator
    float d0 = 0.f, d1 = 0.f, d2 = 0.f, d3 = 0.f;
    for (int e = o0 + lane; e < o1; e += 32) {
        int s = g_srcs[e];
        float4 as = *(const float4*)&g_asrc[s * 4];
        float e0 = __expf(lrelu(as.x + ad.x));
        float e1 = __expf(lrelu(as.y + ad.y));
        float e2 = __expf(lrelu(as.z + ad.z));
        float e3 = __expf(lrelu(as.w + ad.w));
        *(float4*)&g_ex[(size_t)e * 4] = make_float4(e0, e1, e2, e3);
        d0 += e0; d1 += e1; d2 += e2; d3 += e3;
    }
#pragma unroll
    for (int off = 16; off > 0; off >>= 1) {
        d0 += __shfl_xor_sync(0xffffffffu, d0, off);
        d1 += __shfl_xor_sync(0xffffffffu, d1, off);
        d2 += __shfl_xor_sync(0xffffffffu, d2, off);
        d3 += __shfl_xor_sync(0xffffffffu, d3, off);
    }
    float inv0 = __frcp_rn(d0 + se0);
    float inv1 = __frcp_rn(d1 + se1);
    float inv2 = __frcp_rn(d2 + se2);
    float inv3 = __frcp_rn(d3 + se3);

    int col = lane * 2;
    float acc0 = 0.f, acc1 = 0.f;
    // self-loop contribution
    {
        float a0 = se0 * inv0, a1 = se1 * inv1, a2 = se2 * inv2, a3 = se3 * inv3;
        const __nv_bfloat16* row = &g_xp[(size_t)n * 256];
        float2 p;
        p = bf2f(*(const unsigned*)&row[col]);        acc0 += a0 * p.x; acc1 += a0 * p.y;
        p = bf2f(*(const unsigned*)&row[64 + col]);   acc0 += a1 * p.x; acc1 += a1 * p.y;
        p = bf2f(*(const unsigned*)&row[128 + col]);  acc0 += a2 * p.x; acc1 += a2 * p.y;
        p = bf2f(*(const unsigned*)&row[192 + col]);  acc0 += a3 * p.x; acc1 += a3 * p.y;
    }
    // loop2: whole-warp per edge, 2-edge unroll for MLP
    int e = o0;
    for (; e + 2 <= o1; e += 2) {
        int s0 = g_srcs[e], s1 = g_srcs[e + 1];
        float4 exA = *(const float4*)&g_ex[(size_t)e * 4];
        float4 exB = *(const float4*)&g_ex[(size_t)(e + 1) * 4];
        const __nv_bfloat16* rowA = &g_xp[(size_t)s0 * 256];
        const __nv_bfloat16* rowB = &g_xp[(size_t)s1 * 256];
        unsigned uA0 = *(const unsigned*)&rowA[col];
        unsigned uA1 = *(const unsigned*)&rowA[64 + col];
        unsigned uA2 = *(const unsigned*)&rowA[128 + col];
        unsigned uA3 = *(const unsigned*)&rowA[192 + col];
        unsigned uB0 = *(const unsigned*)&rowB[col];
        unsigned uB1 = *(const unsigned*)&rowB[64 + col];
        unsigned uB2 = *(const unsigned*)&rowB[128 + col];
        unsigned uB3 = *(const unsigned*)&rowB[192 + col];
        float aA0 = exA.x * inv0, aA1 = exA.y * inv1, aA2 = exA.z * inv2, aA3 = exA.w * inv3;
        float aB0 = exB.x * inv0, aB1 = exB.y * inv1, aB2 = exB.z * inv2, aB3 = exB.w * inv3;
        float2 p;
        p = bf2f(uA0); acc0 += aA0 * p.x; acc1 += aA0 * p.y;
        p = bf2f(uA1); acc0 += aA1 * p.x; acc1 += aA1 * p.y;
        p = bf2f(uA2); acc0 += aA2 * p.x; acc1 += aA2 * p.y;
        p = bf2f(uA3); acc0 += aA3 * p.x; acc1 += aA3 * p.y;
        p = bf2f(uB0); acc0 += aB0 * p.x; acc1 += aB0 * p.y;
        p = bf2f(uB1); acc0 += aB1 * p.x; acc1 += aB1 * p.y;
        p = bf2f(uB2); acc0 += aB2 * p.x; acc1 += aB2 * p.y;
        p = bf2f(uB3); acc0 += aB3 * p.x; acc1 += aB3 * p.y;
    }
    if (e < o1) {
        int s = g_srcs[e];
        float4 ex = *(const float4*)&g_ex[(size_t)e * 4];
        float a0 = ex.x * inv0, a1 = ex.y * inv1, a2 = ex.z * inv2, a3 = ex.w * inv3;
        const __nv_bfloat16* row = &g_xp[(size_t)s * 256];
        float2 p;
        p = bf2f(*(const unsigned*)&row[col]);        acc0 += a0 * p.x; acc1 += a0 * p.y;
        p = bf2f(*(const unsigned*)&row[64 + col]);   acc0 += a1 * p.x; acc1 += a1 * p.y;
        p = bf2f(*(const unsigned*)&row[128 + col]);  acc0 += a2 * p.x; acc1 += a2 * p.y;
        p = bf2f(*(const unsigned*)&row[192 + col]);  acc0 += a3 * p.x; acc1 += a3 * p.y;
    }
    // head mean + bias + relu
    float r0 = fmaxf(acc0 * 0.25f + bias[col], 0.f);
    float r1 = fmaxf(acc1 * 0.25f + bias[col + 1], 0.f);
    int gph = ldidx(batch, n, g_b64, GG);
    red2(&g_pool[gph * 64 + col], r0, r1);
    if (lane == 0) atomicAdd(&g_cnt[gph], 1.0f);
}

// ---------------- K5: per-graph mean + MLP head + sigmoid ----------------
__global__ void k_head(const float* __restrict__ w1, const float* __restrict__ b1,
                       const float* __restrict__ w2, const float* __restrict__ b2,
                       float* __restrict__ out) {
    __shared__ float w1s[64 * 64];
    __shared__ float b1s[64];
    __shared__ float w2s[64];
    int t = threadIdx.x;
    for (int i = t; i < 64 * 64; i += 128) w1s[i] = w1[i];
    if (t < 64) { b1s[t] = b1[t]; w2s[t] = w2[t]; }
    __syncthreads();
    if (t < GG) {
        float cnt = fmaxf(g_cnt[t], 1.0f);
        float inv = 1.0f / cnt;
        float gv[64];
#pragma unroll
        for (int c = 0; c < 64; c++) gv[c] = g_pool[t * 64 + c] * inv;
        float z = b2[0];
        for (int k = 0; k < 64; k++) {
            float a = b1s[k];
#pragma unroll
            for (int c = 0; c < 64; c++) a += gv[c] * w1s[c * 64 + k];
            a = fmaxf(a, 0.f);
            z += a * w2s[k];
        }
        out[t] = 1.0f / (1.0f + expf(-z));
    }
}

// ---------------- launcher ----------------
extern "C" void kernel_launch(void* const* d_in, const int* in_sizes, int n_in,
                              void* d_out, int out_size) {
    const float* x       = (const float*)d_in[0];
    const float* W       = (const float*)d_in[1];
    const float* att_src = (const float*)d_in[2];
    const float* att_dst = (const float*)d_in[3];
    const float* bias    = (const float*)d_in[4];
    const float* w1      = (const float*)d_in[5];
    const float* b1      = (const float*)d_in[6];
    const float* w2      = (const float*)d_in[7];
    const float* b2      = (const float*)d_in[8];
    const void*  ei      = d_in[9];
    const void*  bat     = d_in[10];

    k_detect<<<1, 256>>>((const int*)ei, (const int*)bat);
    k_zero<<<200, 512>>>();
    k_hist<<<(EE + 255) / 256, 256>>>(ei);
    k_scanA<<<NB, 1024>>>();
    k_scanB<<<1, 128>>>();
    k_scanC<<<NB, 1024>>>();
    k_scatter<<<(EE + 255) / 256, 256>>>(ei);
    dim3 gg((NN + 127) / 128, 2);
    k_gemm<<<gg, 256>>>(x, W, att_src, att_dst);
    k_node_csr<<<(NN * 32 + 255) / 256, 256>>>(bat, bias);
    k_head<<<1, 128>>>(w1, b1, w2, b2, (float*)d_out);
}